// round 16
// baseline (speedup 1.0000x reference)
#include <cuda_runtime.h>
#include <cuda_fp16.h>
#include <math.h>
#include <stdint.h>

// ============================================================================
// Problem constants (fixed by reference setup_inputs)
// ============================================================================
#define NTEST  8192
#define NTRAIN 8192
#define DIM    256

#define TM  128                                  // supertile M
#define TNS 256                                  // supertile N
#define N_COL_ST (NTRAIN / TNS)                  // 32
#define TOT_ST   ((NTEST / TM) * N_COL_ST)       // 2048 supertiles
#define GRID 296                                 // 2 balanced waves
#define A_TILE_BYTES 65536                       // 128 x 256 f16
#define B_CHUNK_BYTES 65536                      // 256 rows x 128 K f16

// Scratch (__device__ globals: allocation-free rule)
// g_At: row-tile-major pre-swizzled (tile rt: 128 rows x 256 K, 64KB).
// g_Bt: (coltile, khalf)-major pre-swizzled chunks (256 rows x 128 K, 64KB;
//       2 kc sub-tiles of 256x128B at stride 32KB).
__device__ float g_XX[NTEST];
__device__ float g_YY[NTRAIN];
__device__ int   g_sat = 0;   // sticky: norm too large for f16-acc bound -> exact path
__device__ __align__(128) __half g_At[NTEST  * DIM];
__device__ __align__(128) __half g_Bt[NTRAIN * DIM];

// ============================================================================
// helpers
// ============================================================================
__device__ __forceinline__ uint32_t smem_u32(const void* p) {
    uint32_t a;
    asm("{ .reg .u64 t; cvta.to.shared.u64 t, %1; cvt.u32.u64 %0, t; }" : "=r"(a) : "l"(p));
    return a;
}
__device__ __forceinline__ void cp16(uint32_t dst, const void* src) {
    asm volatile("cp.async.cg.shared.global [%0], [%1], 16;" :: "r"(dst), "l"(src));
}
#define CP_COMMIT() asm volatile("cp.async.commit_group;" ::: "memory")

__device__ __forceinline__ void ldsm_x4(uint32_t (&r)[4], uint32_t addr) {
    asm volatile("ldmatrix.sync.aligned.m8n8.x4.shared.b16 {%0,%1,%2,%3}, [%4];"
                 : "=r"(r[0]), "=r"(r[1]), "=r"(r[2]), "=r"(r[3]) : "r"(addr));
}
// f16 x f16 -> f16 accumulate (D/C packed as 2x f16x2)
__device__ __forceinline__ void mma_f16acc(uint32_t (&c)[2], const uint32_t (&a)[4],
                                           uint32_t b0, uint32_t b1) {
    asm volatile(
        "mma.sync.aligned.m16n8k16.row.col.f16.f16.f16.f16 "
        "{%0,%1}, {%2,%3,%4,%5}, {%6,%7}, {%0,%1};"
        : "+r"(c[0]), "+r"(c[1])
        : "r"(a[0]), "r"(a[1]), "r"(a[2]), "r"(a[3]), "r"(b0), "r"(b1));
}

// ============================================================================
// Kernel 1: norms + f16 conversion into pre-swizzled layouts + guard + out init
// ============================================================================
__global__ void gp_precompute_kernel(const float* __restrict__ Xtest,
                                     const float* __restrict__ Xtrain,
                                     const float* __restrict__ mean_const,
                                     float* __restrict__ out)
{
    const int warp = threadIdx.x >> 5;
    const int lane = threadIdx.x & 31;
    int row = blockIdx.x * 8 + warp;
    if (row >= NTEST + NTRAIN) return;

    const bool isTest = (row < NTEST);
    const float* X = isTest ? Xtest : Xtrain;
    if (!isTest) row -= NTEST;

    // lane handles 8 consecutive floats (16B chunk: c16 = lane, 0..31)
    const float4* p4 = (const float4*)(X + (size_t)row * DIM) + 2 * lane;
    const float4 v0 = p4[0], v1 = p4[1];
    float v[8] = {v0.x, v0.y, v0.z, v0.w, v1.x, v1.y, v1.z, v1.w};

    float s = 0.f;
    __half h[8];
    #pragma unroll
    for (int j = 0; j < 8; j++) {
        s = fmaf(v[j], v[j], s);
        h[j] = __float2half_rn(v[j]);
    }

    if (isTest) {
        // A layout: row-tile rt = row>>7, lr = row&127, c16 = lane (full K).
        const int rt = row >> 7, lr = row & 127, c16 = lane;
        const uint32_t off = (uint32_t)(((c16 >> 3) << 14) + (lr << 7)
                            + (((c16 & 7) << 4) ^ ((lr & 7) << 4)));
        *(uint4*)((char*)g_At + (size_t)rt * A_TILE_BYTES + off) = *(const uint4*)h;
    } else {
        // B layout: chunk (ct*2 + kh), lr = row&255, c16l = lane&15, kh = lane>>4.
        const int ct = row >> 8, lr = row & 255;
        const int kh = lane >> 4, c16l = lane & 15;
        const uint32_t off = (uint32_t)(((c16l >> 3) << 15) + (lr << 7)
                            + (((c16l & 7) << 4) ^ ((lr & 7) << 4)));
        *(uint4*)((char*)g_Bt + (size_t)(ct * 2 + kh) * B_CHUNK_BYTES + off) = *(const uint4*)h;
    }

    #pragma unroll
    for (int o = 16; o > 0; o >>= 1) s += __shfl_xor_sync(0xffffffffu, s, o);
    if (lane == 0) {
        if (isTest) { g_XX[row] = s; out[row] = *mean_const; }
        else          g_YY[row] = s;
        if (!(s <= 30000.f)) atomicOr(&g_sat, 1);  // keep f16 partials < 65504
    }
}

// ============================================================================
// Kernel 2: f16 HMMA (f16 acc) screening GEMM, 64x64 warp tiles.
// 256 threads, 8 warps in 2(M)x4(N); supertile 128x256. A resident (64KB),
// B in K-half chunks (64KB) double-buffered; acc persists across 2 chunks.
// Screen margin: |ds| <= 0.02*q + 0.05 (rigorous f16 input+accum bound).
// ============================================================================
__global__ __launch_bounds__(256, 1)
void gp_hmma_kernel(const float* __restrict__ Xtest,
                    const float* __restrict__ Xtrain,
                    const float* __restrict__ mu,
                    const float* __restrict__ ls_p,
                    const float* __restrict__ sv_p,
                    float* __restrict__ out)
{
    extern __shared__ char dsm[];
    __shared__ float s_yy[2][TNS];
    __shared__ float s_mu[2][TNS];

    const int tid  = threadIdx.x;
    const int wid  = tid >> 5;
    const int lane = tid & 31;
    const int bid  = blockIdx.x;

    const uint32_t dsm_u = smem_u32(dsm);
    const uint32_t uA  = (dsm_u + 1023u) & ~1023u;
    const uint32_t uC0 = uA  + 65536u;
    const uint32_t uC1 = uC0 + 65536u;

    const int warp_m = (wid & 1) * 64;   // 2 warps along M
    const int warp_n = (wid >> 1) * 64;  // 4 warps along N

    // ldmatrix lane geometry
    const int rA0   = warp_m + (lane & 15);
    const uint32_t swA = (uint32_t)((rA0 & 7) << 4);
    const uint32_t aKl = (uint32_t)((lane >> 4) << 4);
    const int rB0   = warp_n + (lane & 7) + ((lane >> 4) << 3);
    const uint32_t swB = (uint32_t)((rB0 & 7) << 4);
    const uint32_t bKl = (uint32_t)(((lane >> 3) & 1) << 4);

    uint32_t rbaseA[4], rbaseB[4];
    #pragma unroll
    for (int mf = 0; mf < 4; mf++) rbaseA[mf] = uA + (uint32_t)((rA0 + 16 * mf) << 7);
    #pragma unroll
    for (int np = 0; np < 4; np++) rbaseB[np] = (uint32_t)((rB0 + 16 * np) << 7);

    const float l      = *ls_p;
    const float negInv = -0.5f / (l * l);
    const float sCut   = 211.0f * l * l;   // expf == exactly 0 above this
    const float sv     = *sv_p;
    const bool  force  = (g_sat != 0);

    const int t_begin = (int)(((long long)bid     * TOT_ST) / GRID);
    const int t_end   = (int)(((long long)(bid+1) * TOT_ST) / GRID);

    // Linear coalesced 64KB fill (gmem pre-swizzled): 4096 cp16, 16 per thread.
    auto fill64k = [&](uint32_t ubase, const char* src) {
        #pragma unroll
        for (int q0 = 0; q0 < 16; q0++) {
            const uint32_t o = (uint32_t)(q0 * 256 + tid) * 16u;
            cp16(ubase + o, src + o);
        }
    };

    int i = t_begin;
    while (i < t_end) {
        const int rt      = i >> 5;
        const int seg_end = min(t_end, (rt + 1) << 5);
        const int n       = seg_end - i;
        const int row0    = rt * TM;

        fill64k(uA, (const char*)g_At + (size_t)rt * A_TILE_BYTES);
        CP_COMMIT();
        {
            const int ct0 = i & 31;
            fill64k(uC0, (const char*)g_Bt + (size_t)(ct0 * 2) * B_CHUNK_BYTES);
            CP_COMMIT();
            s_yy[0][tid] = g_YY[ct0 * TNS + tid];
            s_mu[0][tid] = mu[ct0 * TNS + tid];
        }

        uint32_t acc[4][8][2];
        const int nch = 2 * n;               // 2 K-half chunks per coltile

        for (int j = 0; j < nch; j++) {
            const int ct = j >> 1;
            const int kh = j & 1;
            const uint32_t uC = (j & 1) ? uC1 : uC0;

            if (j + 1 < nch) {               // prefetch next chunk
                const int ct2 = (j + 1) >> 1, kh2 = (j + 1) & 1;
                const int ctg = (i + ct2) & 31;
                fill64k((j & 1) ? uC0 : uC1,
                        (const char*)g_Bt + (size_t)(ctg * 2 + kh2) * B_CHUNK_BYTES);
                CP_COMMIT();
                if (kh2 == 0) {              // yy/mu for next coltile
                    s_yy[ct2 & 1][tid] = g_YY[ctg * TNS + tid];
                    s_mu[ct2 & 1][tid] = mu[ctg * TNS + tid];
                }
            }
            if (j + 1 < nch) asm volatile("cp.async.wait_group 1;" ::: "memory");
            else             asm volatile("cp.async.wait_group 0;" ::: "memory");
            __syncthreads();

            if (kh == 0) {
                #pragma unroll
                for (int mf = 0; mf < 4; mf++)
                    #pragma unroll
                    for (int nf = 0; nf < 8; nf++) { acc[mf][nf][0] = 0u; acc[mf][nf][1] = 0u; }
            }

            // ---- 8 k-steps, fragment double-buffered: 8 LDSM -> 32 HMMA ----
            uint32_t a[2][4][4], b[2][4][4];

            auto ld_frags = [&](int kk, uint32_t (&af)[4][4], uint32_t (&bf)[4][4]) {
                const int kg = kh * 8 + kk;  // global k-step for A (full-K tile)
                const uint32_t oA = (uint32_t)(((kg >> 2) << 14)
                                   + ((((uint32_t)(kg & 3) << 5) + aKl) ^ swA));
                const uint32_t oB = (uint32_t)(((kk >> 2) << 15)
                                   + ((((uint32_t)(kk & 3) << 5) + bKl) ^ swB));
                #pragma unroll
                for (int mf = 0; mf < 4; mf++) ldsm_x4(af[mf], rbaseA[mf] + oA);
                #pragma unroll
                for (int np = 0; np < 4; np++) ldsm_x4(bf[np], uC + rbaseB[np] + oB);
            };

            ld_frags(0, a[0], b[0]);
            #pragma unroll
            for (int kk = 0; kk < 8; kk++) {
                const int cur = kk & 1;
                if (kk < 7) ld_frags(kk + 1, a[cur ^ 1], b[cur ^ 1]);
                #pragma unroll
                for (int mf = 0; mf < 4; mf++)
                    #pragma unroll
                    for (int nf = 0; nf < 8; nf++)
                        mma_f16acc(acc[mf][nf], a[cur][mf],
                                   b[cur][nf >> 1][(nf & 1) * 2], b[cur][nf >> 1][(nf & 1) * 2 + 1]);
            }

            if (kh == 1) {
                // ---- epilogue: warp-level rigorous screen over 64x64 ----
                const int bufy = ct & 1;
                __half2 m2 = *(const __half2*)&acc[0][0][0];
                #pragma unroll
                for (int mf = 0; mf < 4; mf++)
                    #pragma unroll
                    for (int nf = 0; nf < 8; nf++) {
                        m2 = __hmax2(m2, *(const __half2*)&acc[mf][nf][0]);
                        m2 = __hmax2(m2, *(const __half2*)&acc[mf][nf][1]);
                    }
                float cmax = fmaxf(__low2float(m2), __high2float(m2));
                #pragma unroll
                for (int o = 16; o > 0; o >>= 1) cmax = fmaxf(cmax, __shfl_xor_sync(0xffffffffu, cmax, o));

                // xv reloaded here (not live through the k-loop)
                float xv[8];
                #pragma unroll
                for (int idx = 0; idx < 8; idx++)
                    xv[idx] = g_XX[row0 + warp_m + (idx >> 1) * 16 + (lane >> 2) + 8 * (idx & 1)];
                float xmin = xv[0];
                #pragma unroll
                for (int idx = 1; idx < 8; idx++) xmin = fminf(xmin, xv[idx]);
                float ymin = fminf(s_yy[bufy][warp_n + lane], s_yy[bufy][warp_n + 32 + lane]);
                #pragma unroll
                for (int o = 16; o > 0; o >>= 1) {
                    xmin = fminf(xmin, __shfl_xor_sync(0xffffffffu, xmin, o));
                    ymin = fminf(ymin, __shfl_xor_sync(0xffffffffu, ymin, o));
                }

                const float qmin  = xmin + ymin;                       // q >= 0
                const float lbmin = fmaf(-0.02f, qmin, fmaf(-2.f, cmax, qmin)) - 0.05f;

                if (force || lbmin < sCut) {   // per-element screen + exact recompute
                    const int n0 = ((i + ct) & 31) * TNS;
                    #pragma unroll 1
                    for (int mf = 0; mf < 4; mf++)
                        for (int nf = 0; nf < 8; nf++)
                            for (int jj = 0; jj < 2; jj++) {
                                const float2 cv = __half22float2(*(const __half2*)&acc[mf][nf][jj]);
                                #pragma unroll
                                for (int p = 0; p < 2; p++) {
                                    const float c  = p ? cv.y : cv.x;
                                    const int colL = warp_n + nf * 8 + 2 * (lane & 3) + p;
                                    const float q  = xv[mf * 2 + jj] + s_yy[bufy][colL];
                                    const float s  = fmaf(-2.f, c, q);
                                    const float lb = fmaf(-0.02f, q, s) - 0.05f;
                                    if (force || lb < sCut) {
                                        const int rg = row0 + warp_m + mf * 16 + (lane >> 2) + 8 * jj;
                                        const int cg = n0 + colL;
                                        const float* xr = Xtest  + (size_t)rg * DIM;
                                        const float* yr = Xtrain + (size_t)cg * DIM;
                                        float cr = 0.f;
                                        #pragma unroll 8
                                        for (int d = 0; d < DIM; d++) cr = fmaf(xr[d], yr[d], cr);
                                        const float se = fmaxf(fmaf(-2.f, cr, g_XX[rg] + g_YY[cg]), 0.f);
                                        const float ev = expf(se * negInv);
                                        if (ev != 0.f)
                                            atomicAdd(&out[rg], sv * ev * s_mu[bufy][colL]);
                                    }
                                }
                            }
                }
            }
            __syncthreads();   // compute/epilogue done before buffer reuse
        }
        i = seg_end;
    }
}

// ============================================================================
// kernel_launch: inputs in metadata order:
//   0 Xtest, 1 Xtrain, 2 mu, 3 mean_const, 4 lengthscale, 5 signal_var
// ============================================================================
extern "C" void kernel_launch(void* const* d_in, const int* in_sizes, int n_in,
                              void* d_out, int out_size)
{
    const float* Xtest      = (const float*)d_in[0];
    const float* Xtrain     = (const float*)d_in[1];
    const float* mu         = (const float*)d_in[2];
    const float* mean_const = (const float*)d_in[3];
    const float* lengthsc   = (const float*)d_in[4];
    const float* signal_var = (const float*)d_in[5];
    float* out = (float*)d_out;

    const int DYN = 3 * 65536 + 1024;   // A + chunk0 + chunk1 + align slack
    cudaFuncSetAttribute(gp_hmma_kernel, cudaFuncAttributeMaxDynamicSharedMemorySize, DYN);

    gp_precompute_kernel<<<(NTEST + NTRAIN) / 8, 256>>>(Xtest, Xtrain, mean_const, out);
    gp_hmma_kernel<<<GRID, 256, DYN>>>(Xtest, Xtrain, mu, lengthsc, signal_var, out);
}